// round 11
// baseline (speedup 1.0000x reference)
#include <cuda_runtime.h>
#include <cuda_fp16.h>
#include <mma.h>
#include <math.h>

using namespace nvcuda;

#define NMAX 50000
#define EMAX 800000
#define GMAX 1000
#define LEAK 0.01f
#define EPS  1e-5f
#define CDIV(a,b) (((a)+(b)-1)/(b))

// ---------------- scratch ----------------------------------------------------
__device__ float g_bufA[NMAX*128];
__device__ float g_bufB[NMAX*128];
__device__ float g_bufC[NMAX*128];
__device__ __half g_wh[128*128];    // fp16 W1
__device__ __half g_whc[128*128];   // fp16 [Wl | Wr]
__device__ int   g_indeg[NMAX];
__device__ int   g_off[NMAX+1];
__device__ int   g_cur[NMAX];
__device__ int   g_csr[EMAX];
__device__ float g_dinv[NMAX];     // rsqrt(indeg+1)
__device__ float g_rcnt[NMAX];     // 1/max(indeg,1)
__device__ float g_colsum[256];
__device__ float g_colsq[256];
__device__ float g_scale[256];
__device__ float g_shift[256];
__device__ float g_pool[GMAX*32];

// ---------------- degree / CSR (4 edges per thread for atomic MLP) -----------
__global__ void deg_kernel(const int* __restrict__ dst, int nE) {
    int e = (blockIdx.x * blockDim.x + threadIdx.x) * 4;
#pragma unroll
    for (int i = 0; i < 4; i++)
        if (e + i < nE) atomicAdd(&g_indeg[dst[e + i]], 1);
}

__global__ void scan_kernel(int n) {
    __shared__ int part[1024];
    int tid = threadIdx.x;
    int chunk = CDIV(n, 1024);
    int start = tid * chunk;
    int end   = min(start + chunk, n);
    int s = 0;
    for (int i = start; i < end; i++) s += g_indeg[i];
    part[tid] = s;
    __syncthreads();
    for (int off = 1; off < 1024; off <<= 1) {
        int v = (tid >= off) ? part[tid - off] : 0;
        __syncthreads();
        part[tid] += v;
        __syncthreads();
    }
    int run = (tid > 0) ? part[tid - 1] : 0;
    for (int i = start; i < end; i++) {
        int d = g_indeg[i];
        g_off[i] = run;
        g_cur[i] = run;
        g_dinv[i] = rsqrtf((float)(d + 1));
        g_rcnt[i] = 1.0f / (float)(d > 0 ? d : 1);
        run += d;
    }
    if (end == n && start < n) g_off[n] = run;
}

__global__ void fill_csr_kernel(const int* __restrict__ src,
                                const int* __restrict__ dst, int nE) {
    int e = (blockIdx.x * blockDim.x + threadIdx.x) * 4;
#pragma unroll
    for (int i = 0; i < 4; i++) {
        if (e + i < nE) {
            int p = atomicAdd(&g_cur[dst[e + i]], 1);
            g_csr[p] = src[e + i];
        }
    }
}

// ---------------- fp32 -> fp16 weight conversions ----------------------------
__global__ void f2h_kernel(const float* __restrict__ X, __half* __restrict__ Xh,
                           int total4) {
    int i = blockIdx.x * blockDim.x + threadIdx.x;
    if (i < total4) {
        float4 v = ((const float4*)X)[i];
        __half2 h0 = __floats2half2_rn(v.x, v.y);
        __half2 h1 = __floats2half2_rn(v.z, v.w);
        uint2 u;
        *(__half2*)&u.x = h0;
        *(__half2*)&u.y = h1;
        ((uint2*)Xh)[i] = u;
    }
}

__global__ void whc_kernel(const float* __restrict__ Wl, const float* __restrict__ Wr,
                           __half* __restrict__ Whc) {
    int i = blockIdx.x * blockDim.x + threadIdx.x;
    if (i < 128 * 128) {
        int k = i >> 7, c = i & 127;
        float v = (c < 64) ? Wl[k * 64 + c] : Wr[k * 64 + (c - 64)];
        Whc[i] = __float2half_rn(v);
    }
}

// ---------------- GEMM1 via tensor cores: Yh = half(X@Wh * dinv) -------------
// fp32 X converted to fp16 during smem staging. block 256 (8 warps), 32 rows.
__global__ void gemm1_wmma(const float* __restrict__ X, const __half* __restrict__ Wh,
                           __half* __restrict__ Yh, int n) {
    __shared__ __half as[32 * 128];
    __shared__ float  cs[32 * 128];
    int tid = threadIdx.x;
    int r0  = blockIdx.x * 32;
    for (int i = tid; i < 1024; i += 256) {
        int row = r0 + (i >> 5);
        int k4  = i & 31;
        float4 v = (row < n) ? ((const float4*)X)[(size_t)row * 32 + k4]
                             : make_float4(0.f, 0.f, 0.f, 0.f);
        __half2 h0 = __floats2half2_rn(v.x, v.y);
        __half2 h1 = __floats2half2_rn(v.z, v.w);
        uint2 u;
        *(__half2*)&u.x = h0;
        *(__half2*)&u.y = h1;
        ((uint2*)as)[i] = u;
    }
    __syncthreads();
    int warp = tid >> 5;
    int rw = warp >> 2, cw = warp & 3;
    wmma::fragment<wmma::matrix_a, 16, 16, 16, __half, wmma::row_major> fa;
    wmma::fragment<wmma::matrix_b, 16, 16, 16, __half, wmma::row_major> fb0, fb1;
    wmma::fragment<wmma::accumulator, 16, 16, 16, float> fc0, fc1;
    wmma::fill_fragment(fc0, 0.0f);
    wmma::fill_fragment(fc1, 0.0f);
    const __half* abase = as + rw * 16 * 128;
#pragma unroll
    for (int k = 0; k < 128; k += 16) {
        wmma::load_matrix_sync(fa, abase + k, 128);
        wmma::load_matrix_sync(fb0, Wh + k * 128 + cw * 32, 128);
        wmma::load_matrix_sync(fb1, Wh + k * 128 + cw * 32 + 16, 128);
        wmma::mma_sync(fc0, fa, fb0, fc0);
        wmma::mma_sync(fc1, fa, fb1, fc1);
    }
    wmma::store_matrix_sync(cs + rw * 16 * 128 + cw * 32,      fc0, 128, wmma::mem_row_major);
    wmma::store_matrix_sync(cs + rw * 16 * 128 + cw * 32 + 16, fc1, 128, wmma::mem_row_major);
    __syncthreads();
    for (int i = tid; i < 2048; i += 256) {
        int row = i >> 6, c2 = i & 63;
        int grow = r0 + row;
        if (grow < n) {
            float d = g_dinv[grow];
            float v0 = cs[row * 128 + c2 * 2 + 0] * d;
            float v1 = cs[row * 128 + c2 * 2 + 1] * d;
            ((__half2*)Yh)[(size_t)grow * 64 + c2] = __floats2half2_rn(v0, v1);
        }
    }
}

// ---------------- dual GEMM via tensor cores ---------------------------------
// h = lrelu(bn1(X)) fp16 tile; C = h @ [Wl|Wr]; cols<64 -> P(half), >=64 -> Q(f32).
__global__ void dual_gemm_wmma(const float* __restrict__ X, const __half* __restrict__ Whc,
                               __half* __restrict__ P, float* __restrict__ Q, int n) {
    __shared__ __half as[32 * 128];
    __shared__ float  cs[32 * 128];
    int tid = threadIdx.x;
    int r0  = blockIdx.x * 32;
    for (int i = tid; i < 1024; i += 256) {
        int row = r0 + (i >> 5);
        int k4  = i & 31;
        float4 v = (row < n) ? ((const float4*)X)[(size_t)row * 32 + k4]
                             : make_float4(0.f, 0.f, 0.f, 0.f);
        float4 sc = ((const float4*)g_scale)[k4];
        float4 sh = ((const float4*)g_shift)[k4];
        float a;
        a = fmaf(v.x, sc.x, sh.x); v.x = (a >= 0.f) ? a : LEAK * a;
        a = fmaf(v.y, sc.y, sh.y); v.y = (a >= 0.f) ? a : LEAK * a;
        a = fmaf(v.z, sc.z, sh.z); v.z = (a >= 0.f) ? a : LEAK * a;
        a = fmaf(v.w, sc.w, sh.w); v.w = (a >= 0.f) ? a : LEAK * a;
        __half2 h0 = __floats2half2_rn(v.x, v.y);
        __half2 h1 = __floats2half2_rn(v.z, v.w);
        uint2 u;
        *(__half2*)&u.x = h0;
        *(__half2*)&u.y = h1;
        ((uint2*)as)[i] = u;
    }
    __syncthreads();
    int warp = tid >> 5;
    int rw = warp >> 2, cw = warp & 3;
    wmma::fragment<wmma::matrix_a, 16, 16, 16, __half, wmma::row_major> fa;
    wmma::fragment<wmma::matrix_b, 16, 16, 16, __half, wmma::row_major> fb0, fb1;
    wmma::fragment<wmma::accumulator, 16, 16, 16, float> fc0, fc1;
    wmma::fill_fragment(fc0, 0.0f);
    wmma::fill_fragment(fc1, 0.0f);
    const __half* abase = as + rw * 16 * 128;
#pragma unroll
    for (int k = 0; k < 128; k += 16) {
        wmma::load_matrix_sync(fa, abase + k, 128);
        wmma::load_matrix_sync(fb0, Whc + k * 128 + cw * 32, 128);
        wmma::load_matrix_sync(fb1, Whc + k * 128 + cw * 32 + 16, 128);
        wmma::mma_sync(fc0, fa, fb0, fc0);
        wmma::mma_sync(fc1, fa, fb1, fc1);
    }
    wmma::store_matrix_sync(cs + rw * 16 * 128 + cw * 32,      fc0, 128, wmma::mem_row_major);
    wmma::store_matrix_sync(cs + rw * 16 * 128 + cw * 32 + 16, fc1, 128, wmma::mem_row_major);
    __syncthreads();
    for (int i = tid; i < 4096; i += 256) {
        int row = i >> 7, c = i & 127;
        int grow = r0 + row;
        if (grow < n) {
            float v = cs[i];
            if (c < 64) P[(size_t)grow * 64 + c] = __float2half_rn(v);
            else        Q[(size_t)grow * 64 + (c - 64)] = v;
        }
    }
}

// ---------------- small GEMM (M=32): Y = lrelu(bn(X)) @ W, * dinv ------------
template <int K, int M, int ROWS, int OFF>
__global__ void gemm_small(const float* __restrict__ X, const float* __restrict__ W,
                           float* __restrict__ Y, int n) {
    const int RG  = 128 / M;
    const int BR  = RG * ROWS;
    const int PBR = BR + 4;
    __shared__ float xs[K * PBR];
    int tid = threadIdx.x;
    int r0  = blockIdx.x * BR;
    for (int i = tid; i < BR * K; i += 128) {
        int r = i / K, k = i % K;
        int row = r0 + r;
        float v = (row < n) ? X[row * K + k] : 0.0f;
        v = fmaf(v, g_scale[OFF + k], g_shift[OFF + k]);
        v = (v >= 0.0f) ? v : LEAK * v;
        xs[k * PBR + r] = v;
    }
    __syncthreads();
    int col = tid % M;
    int rg  = tid / M;
    float acc[ROWS];
#pragma unroll
    for (int r = 0; r < ROWS; r++) acc[r] = 0.0f;
#pragma unroll 4
    for (int k = 0; k < K; k++) {
        float w = W[k * M + col];
        const float4* xv = (const float4*)&xs[k * PBR + rg * ROWS];
#pragma unroll
        for (int r4 = 0; r4 < ROWS / 4; r4++) {
            float4 xx = xv[r4];
            acc[r4*4+0] = fmaf(xx.x, w, acc[r4*4+0]);
            acc[r4*4+1] = fmaf(xx.y, w, acc[r4*4+1]);
            acc[r4*4+2] = fmaf(xx.z, w, acc[r4*4+2]);
            acc[r4*4+3] = fmaf(xx.w, w, acc[r4*4+3]);
        }
    }
#pragma unroll
    for (int r = 0; r < ROWS; r++) {
        int row = r0 + rg * ROWS + r;
        if (row < n) Y[row * M + col] = acc[r] * g_dinv[row];
    }
}

// ---------------- CSR gathers (2 nodes/warp, 2 edges/node blocks = MLP 4) ----
__device__ __forceinline__ float4 h4_to_f4(uint2 raw) {
    const __half2* hp = (const __half2*)&raw;
    float2 a = __half22float2(hp[0]);
    float2 b = __half22float2(hp[1]);
    return make_float4(a.x, a.y, b.x, b.y);
}
__device__ __forceinline__ void acc4(float4& a, float4 v) {
    a.x += v.x; a.y += v.y; a.z += v.z; a.w += v.w;
}

__global__ void gather128_gcn_h(const __half* __restrict__ Hin,
                                float* __restrict__ Hout, int n) {
    int w    = (blockIdx.x * blockDim.x + threadIdx.x) >> 5;
    int lane = threadIdx.x & 31;
    int n0 = 2 * w, n1 = 2 * w + 1;
    if (n0 >= n) return;
    bool has1 = (n1 < n);
    const uint2* H2 = (const uint2*)Hin;
    float4 acc0 = h4_to_f4(H2[n0 * 32 + lane]);
    float4 acc1 = make_float4(0.f, 0.f, 0.f, 0.f);
    if (has1) acc1 = h4_to_f4(H2[n1 * 32 + lane]);
    int e0 = g_off[n0], E0 = g_off[n0 + 1];
    int e1 = has1 ? g_off[n1] : 0, E1 = has1 ? g_off[n1 + 1] : 0;
    // 2 edges per node per iteration -> 4 feature loads in flight
    while (e0 + 2 <= E0 && e1 + 2 <= E1) {
        int a0 = __ldg(&g_csr[e0]), a1 = __ldg(&g_csr[e0 + 1]);
        int b0 = __ldg(&g_csr[e1]), b1 = __ldg(&g_csr[e1 + 1]);
        e0 += 2; e1 += 2;
        float4 va0 = h4_to_f4(H2[a0 * 32 + lane]);
        float4 va1 = h4_to_f4(H2[a1 * 32 + lane]);
        float4 vb0 = h4_to_f4(H2[b0 * 32 + lane]);
        float4 vb1 = h4_to_f4(H2[b1 * 32 + lane]);
        acc4(acc0, va0); acc4(acc0, va1);
        acc4(acc1, vb0); acc4(acc1, vb1);
    }
    while (e0 < E0 && e1 < E1) {
        int i0 = __ldg(&g_csr[e0]); e0++;
        int i1 = __ldg(&g_csr[e1]); e1++;
        acc4(acc0, h4_to_f4(H2[i0 * 32 + lane]));
        acc4(acc1, h4_to_f4(H2[i1 * 32 + lane]));
    }
    for (; e0 + 2 <= E0; e0 += 2) {
        int i0 = __ldg(&g_csr[e0]), i1 = __ldg(&g_csr[e0 + 1]);
        acc4(acc0, h4_to_f4(H2[i0 * 32 + lane]));
        acc4(acc0, h4_to_f4(H2[i1 * 32 + lane]));
    }
    for (; e0 < E0; e0++) acc4(acc0, h4_to_f4(H2[__ldg(&g_csr[e0]) * 32 + lane]));
    for (; e1 + 2 <= E1; e1 += 2) {
        int i0 = __ldg(&g_csr[e1]), i1 = __ldg(&g_csr[e1 + 1]);
        acc4(acc1, h4_to_f4(H2[i0 * 32 + lane]));
        acc4(acc1, h4_to_f4(H2[i1 * 32 + lane]));
    }
    for (; e1 < E1; e1++) acc4(acc1, h4_to_f4(H2[__ldg(&g_csr[e1]) * 32 + lane]));
    float d0 = g_dinv[n0];
    ((float4*)Hout)[n0 * 32 + lane] =
        make_float4(acc0.x * d0, acc0.y * d0, acc0.z * d0, acc0.w * d0);
    if (has1) {
        float d1 = g_dinv[n1];
        ((float4*)Hout)[n1 * 32 + lane] =
            make_float4(acc1.x * d1, acc1.y * d1, acc1.z * d1, acc1.w * d1);
    }
}

__global__ void gather64_sage_h(const __half* __restrict__ P, const float* __restrict__ Q,
                                float* __restrict__ Y, int n) {
    int w    = (blockIdx.x * blockDim.x + threadIdx.x) >> 5;
    int lane = threadIdx.x & 31;
    int n0 = 2 * w, n1 = 2 * w + 1;
    if (n0 >= n) return;
    bool has1 = (n1 < n);
    const __half2* P2 = (const __half2*)P;
    float2 acc0 = make_float2(0.f, 0.f);
    float2 acc1 = make_float2(0.f, 0.f);
    int e0 = g_off[n0], E0 = g_off[n0 + 1];
    int e1 = has1 ? g_off[n1] : 0, E1 = has1 ? g_off[n1 + 1] : 0;
    while (e0 + 2 <= E0 && e1 + 2 <= E1) {
        int a0 = __ldg(&g_csr[e0]), a1 = __ldg(&g_csr[e0 + 1]);
        int b0 = __ldg(&g_csr[e1]), b1 = __ldg(&g_csr[e1 + 1]);
        e0 += 2; e1 += 2;
        float2 va0 = __half22float2(P2[a0 * 32 + lane]);
        float2 va1 = __half22float2(P2[a1 * 32 + lane]);
        float2 vb0 = __half22float2(P2[b0 * 32 + lane]);
        float2 vb1 = __half22float2(P2[b1 * 32 + lane]);
        acc0.x += va0.x + va1.x; acc0.y += va0.y + va1.y;
        acc1.x += vb0.x + vb1.x; acc1.y += vb0.y + vb1.y;
    }
    while (e0 < E0 && e1 < E1) {
        int i0 = __ldg(&g_csr[e0]); e0++;
        int i1 = __ldg(&g_csr[e1]); e1++;
        float2 v0 = __half22float2(P2[i0 * 32 + lane]);
        float2 v1 = __half22float2(P2[i1 * 32 + lane]);
        acc0.x += v0.x; acc0.y += v0.y;
        acc1.x += v1.x; acc1.y += v1.y;
    }
    for (; e0 < E0; e0++) {
        float2 v = __half22float2(P2[__ldg(&g_csr[e0]) * 32 + lane]);
        acc0.x += v.x; acc0.y += v.y;
    }
    for (; e1 < E1; e1++) {
        float2 v = __half22float2(P2[__ldg(&g_csr[e1]) * 32 + lane]);
        acc1.x += v.x; acc1.y += v.y;
    }
    float r0 = g_rcnt[n0];
    float2 q0 = ((const float2*)Q)[n0 * 32 + lane];
    ((float2*)Y)[n0 * 32 + lane] = make_float2(fmaf(acc0.x, r0, q0.x), fmaf(acc0.y, r0, q0.y));
    if (has1) {
        float r1 = g_rcnt[n1];
        float2 q1 = ((const float2*)Q)[n1 * 32 + lane];
        ((float2*)Y)[n1 * 32 + lane] = make_float2(fmaf(acc1.x, r1, q1.x), fmaf(acc1.y, r1, q1.y));
    }
}

__global__ void gather32_kernel(const float* __restrict__ Hin,
                                float* __restrict__ Hout, int n) {
    int w    = (blockIdx.x * blockDim.x + threadIdx.x) >> 5;
    int lane = threadIdx.x & 31;
    int n0 = 2 * w, n1 = 2 * w + 1;
    if (n0 >= n) return;
    bool has1 = (n1 < n);
    float acc0 = Hin[n0 * 32 + lane];
    float acc1 = has1 ? Hin[n1 * 32 + lane] : 0.0f;
    int e0 = g_off[n0], E0 = g_off[n0 + 1];
    int e1 = has1 ? g_off[n1] : 0, E1 = has1 ? g_off[n1 + 1] : 0;
    while (e0 + 2 <= E0 && e1 + 2 <= E1) {
        int a0 = __ldg(&g_csr[e0]), a1 = __ldg(&g_csr[e0 + 1]);
        int b0 = __ldg(&g_csr[e1]), b1 = __ldg(&g_csr[e1 + 1]);
        e0 += 2; e1 += 2;
        acc0 += Hin[a0 * 32 + lane] + Hin[a1 * 32 + lane];
        acc1 += Hin[b0 * 32 + lane] + Hin[b1 * 32 + lane];
    }
    while (e0 < E0 && e1 < E1) {
        int i0 = __ldg(&g_csr[e0]); e0++;
        int i1 = __ldg(&g_csr[e1]); e1++;
        acc0 += Hin[i0 * 32 + lane];
        acc1 += Hin[i1 * 32 + lane];
    }
    for (; e0 < E0; e0++) acc0 += Hin[__ldg(&g_csr[e0]) * 32 + lane];
    for (; e1 < E1; e1++) acc1 += Hin[__ldg(&g_csr[e1]) * 32 + lane];
    Hout[n0 * 32 + lane] = acc0 * g_dinv[n0];
    if (has1) Hout[n1 * 32 + lane] = acc1 * g_dinv[n1];
}

// ---------------- batch norm -------------------------------------------------
template <int C, int OFF>
__global__ void bn_stats_kernel(const float* __restrict__ X, long long total) {
    __shared__ float s1[256];
    __shared__ float s2[256];
    int tid = threadIdx.x;
    float sum = 0.0f, sq = 0.0f;
    for (long long i = (long long)blockIdx.x * 256 + tid; i < total;
         i += (long long)gridDim.x * 256) {
        float v = X[i];
        sum += v; sq += v * v;
    }
    s1[tid] = sum; s2[tid] = sq;
    __syncthreads();
    for (int off = 128; off >= C; off >>= 1) {
        if (tid < off) { s1[tid] += s1[tid + off]; s2[tid] += s2[tid + off]; }
        __syncthreads();
    }
    if (tid < C) {
        atomicAdd(&g_colsum[OFF + tid], s1[tid]);
        atomicAdd(&g_colsq[OFF + tid],  s2[tid]);
    }
}

__global__ void bn_finalize_kernel(const float* __restrict__ gamma,
                                   const float* __restrict__ beta, int off, float invn) {
    int c = threadIdx.x;
    float m   = g_colsum[off + c] * invn;
    float var = g_colsq[off + c] * invn - m * m;
    float sc  = gamma[c] * rsqrtf(var + EPS);
    g_scale[off + c] = sc;
    g_shift[off + c] = beta[c] - m * sc;
}

// ---------------- pool + link ------------------------------------------------
__global__ void pool_kernel(const float* __restrict__ H, const int* __restrict__ batch,
                            const float* __restrict__ b4, int n) {
    int t = blockIdx.x * blockDim.x + threadIdx.x;
    int node = t / 8, j = t % 8;
    if (node >= n) return;
    int g = batch[node];
    float4 v = ((const float4*)H)[node * 8 + j];
    float4 bb = ((const float4*)b4)[j];
    v.x += bb.x; v.y += bb.y; v.z += bb.z; v.w += bb.w;
    float4* p = ((float4*)g_pool) + g * 8 + j;
    asm volatile("red.global.add.v4.f32 [%0], {%1,%2,%3,%4};"
                 :: "l"(p), "f"(v.x), "f"(v.y), "f"(v.z), "f"(v.w) : "memory");
}

__global__ void link_kernel(const int* __restrict__ li, float* __restrict__ out, int L) {
    int w = (blockIdx.x * blockDim.x + threadIdx.x) / 32;
    int lane = threadIdx.x & 31;
    if (w >= L) return;
    int a = li[w], b = li[L + w];
    float v = g_pool[a * 32 + lane] * g_pool[b * 32 + lane];
#pragma unroll
    for (int off = 16; off > 0; off >>= 1)
        v += __shfl_xor_sync(0xFFFFFFFFu, v, off);
    if (lane == 0) out[w] = 1.0f / (1.0f + expf(-v));
}

// ---------------- launch -----------------------------------------------------
extern "C" void kernel_launch(void* const* d_in, const int* in_sizes, int n_in,
                              void* d_out, int out_size) {
    int base = 4;
    if (n_in >= 20 && in_sizes[4] == 1) base = 5;

    const float* x    = (const float*)d_in[0];
    const int*   ei   = (const int*)d_in[1];
    const int*   batch= (const int*)d_in[2];
    const int*   li   = (const int*)d_in[3];
    const float* W1   = (const float*)d_in[base + 0];
    const float* g1   = (const float*)d_in[base + 2];
    const float* be1  = (const float*)d_in[base + 3];
    const float* Wl2  = (const float*)d_in[base + 4];
    const float* Wr2  = (const float*)d_in[base + 6];
    const float* g2   = (const float*)d_in[base + 7];
    const float* be2  = (const float*)d_in[base + 8];
    const float* W3   = (const float*)d_in[base + 9];
    const float* g3   = (const float*)d_in[base + 11];
    const float* be3  = (const float*)d_in[base + 12];
    const float* W4   = (const float*)d_in[base + 13];
    const float* b4   = (const float*)d_in[base + 14];
    float* out = (float*)d_out;

    const int N = in_sizes[0] / 128;
    const int E = in_sizes[1] / 2;
    const int L = in_sizes[3] / 2;
    const int* src = ei;
    const int* dst = ei + E;
    const float invN = 1.0f / (float)N;

    float *bufA, *bufB, *bufC, *poolp, *colsum, *colsq;
    int* indeg;
    __half *wh, *whc;
    cudaGetSymbolAddress((void**)&bufA,   g_bufA);
    cudaGetSymbolAddress((void**)&bufB,   g_bufB);
    cudaGetSymbolAddress((void**)&bufC,   g_bufC);
    cudaGetSymbolAddress((void**)&indeg,  g_indeg);
    cudaGetSymbolAddress((void**)&poolp,  g_pool);
    cudaGetSymbolAddress((void**)&colsum, g_colsum);
    cudaGetSymbolAddress((void**)&colsq,  g_colsq);
    cudaGetSymbolAddress((void**)&wh,     g_wh);
    cudaGetSymbolAddress((void**)&whc,    g_whc);
    __half* bufAh = (__half*)bufA;

    // ---- setup ----
    cudaMemsetAsync(indeg,  0, N * sizeof(int));
    cudaMemsetAsync(colsum, 0, 256 * sizeof(float));
    cudaMemsetAsync(colsq,  0, 256 * sizeof(float));
    cudaMemsetAsync(poolp,  0, (size_t)GMAX * 32 * sizeof(float));
    deg_kernel<<<CDIV(E, 1024), 256>>>(dst, E);
    scan_kernel<<<1, 1024>>>(N);
    fill_csr_kernel<<<CDIV(E, 1024), 256>>>(src, dst, E);

    // ---- fp16 weight conversions (W1 -> g_wh, [Wl|Wr] -> g_whc) ----
    f2h_kernel<<<CDIV(128 * 32, 256), 256>>>(W1, wh, 128 * 32);
    whc_kernel<<<CDIV(128 * 128, 256), 256>>>(Wl2, Wr2, whc);

    // ---- Layer 1: GCN(128->128) via tensor cores (x converted inline) ----
    gemm1_wmma<<<CDIV(N, 32), 256>>>(x, wh, bufAh, N);       // half(x@W1 * dinv)
    gather128_gcn_h<<<CDIV(CDIV(N, 2) * 32, 256), 256>>>(bufAh, bufB, N);
    bn_stats_kernel<128, 0><<<1024, 256>>>(bufB, (long long)N * 128);
    bn_finalize_kernel<<<1, 128>>>(g1, be1, 0, invN);

    // ---- Layer 2: SAGE(128->64) via tensor cores, aggregation commuted ----
    dual_gemm_wmma<<<CDIV(N, 32), 256>>>(bufB, whc, bufAh, bufC, N);
    gather64_sage_h<<<CDIV(CDIV(N, 2) * 32, 256), 256>>>(bufAh, bufC, bufB, N);
    bn_stats_kernel<64, 128><<<1024, 256>>>(bufB, (long long)N * 64);
    bn_finalize_kernel<<<1, 64>>>(g2, be2, 128, invN);

    // ---- Layer 3: GCN(64->32); BN2 applied on GEMM load ----
    gemm_small<64, 32, 8, 128><<<CDIV(N, 32), 128>>>(bufB, W3, bufA, N);
    gather32_kernel<<<CDIV(CDIV(N, 2) * 32, 256), 256>>>(bufA, bufC, N);
    bn_stats_kernel<32, 192><<<1024, 256>>>(bufC, (long long)N * 32);
    bn_finalize_kernel<<<1, 32>>>(g3, be3, 192, invN);

    // ---- Layer 4: GCN(32->32); BN3 applied on GEMM load; b4 folded into pool ----
    gemm_small<32, 32, 8, 192><<<CDIV(N, 32), 128>>>(bufC, W4, bufA, N);
    gather32_kernel<<<CDIV(CDIV(N, 2) * 32, 256), 256>>>(bufA, bufB, N);

    // ---- pool + link ----
    pool_kernel<<<CDIV(N * 8, 256), 256>>>(bufB, batch, b4, N);
    link_kernel<<<CDIV(L * 32, 256), 256>>>(li, out, L);
}